// round 1
// baseline (speedup 1.0000x reference)
#include <cuda_runtime.h>
#include <math.h>

// Problem constants
#define BB     4
#define TT     2048
#define NTOK   (BB*TT)          // 8192
#define DM     128
#define NH     4
#define DH     32
#define WIN    64
#define DFFN   256
#define DQKV   384
#define TILE   8                // tokens per block in GEMM kernels
#define NBLK   (NTOK/TILE)      // 1024

// Scratch (no cudaMalloc allowed)
__device__ float g_h[NTOK*DM];       // 4 MB
__device__ float g_qkv[NTOK*DQKV];   // 12 MB
__device__ float g_att[NTOK*DM];     // 4 MB

// ---------------------------------------------------------------------------
// Kernel 1: in_proj  (concat -> Linear(16,128) -> ReLU -> Linear(128,128) + PE)
// ---------------------------------------------------------------------------
__global__ void k_inproj(const float* __restrict__ E, const float* __restrict__ rho,
                         const float* __restrict__ W1, const float* __restrict__ b1,
                         const float* __restrict__ W2, const float* __restrict__ b2)
{
    int m0 = blockIdx.x * TILE;
    int t  = threadIdx.x;           // 0..127 = output channel
    __shared__ float xs[TILE][16];
    __shared__ float hid[TILE][DM];

    // load concat(E, rho) for 8 tokens: 128 elements, one per thread
    {
        int m = t >> 4, k = t & 15;
        int r = m0 + m;
        xs[m][k] = (k < 8) ? E[r*8 + k] : rho[r*8 + (k-8)];
    }
    __syncthreads();

    // hidden = relu(x @ W1 + b1)
    {
        float acc[TILE];
        float bv = b1[t];
        #pragma unroll
        for (int m = 0; m < TILE; m++) acc[m] = bv;
        #pragma unroll
        for (int k = 0; k < 16; k++) {
            float w = W1[k*DM + t];
            #pragma unroll
            for (int m = 0; m < TILE; m++) acc[m] = fmaf(xs[m][k], w, acc[m]);
        }
        #pragma unroll
        for (int m = 0; m < TILE; m++) hid[m][t] = fmaxf(acc[m], 0.0f);
    }
    __syncthreads();

    // h = hidden @ W2 + b2 + PE
    {
        float acc[TILE];
        float bv = b2[t];
        #pragma unroll
        for (int m = 0; m < TILE; m++) acc[m] = bv;
        #pragma unroll 8
        for (int k = 0; k < DM; k++) {
            float w = W2[k*DM + t];
            #pragma unroll
            for (int m = 0; m < TILE; m++) acc[m] = fmaf(hid[m][k], w, acc[m]);
        }
        int i = t >> 1;
        float invfreq = __expf(-logf(10000.0f) * (float)i / 64.0f);
        #pragma unroll
        for (int m = 0; m < TILE; m++) {
            int r   = m0 + m;
            int pos = r & (TT - 1);
            float ang = (float)pos * invfreq;
            float pe  = (t & 1) ? cosf(ang) : sinf(ang);
            g_h[r*DM + t] = acc[m] + pe;
        }
    }
}

// ---------------------------------------------------------------------------
// Kernel 2: QKV projection  (h @ Wqkv + bqkv) -> g_qkv (layout [tok][384])
// ---------------------------------------------------------------------------
__global__ void k_qkv(const float* __restrict__ W, const float* __restrict__ bias)
{
    int m0 = blockIdx.x * TILE;
    int t  = threadIdx.x;
    __shared__ float hs[TILE][DM];
    #pragma unroll
    for (int m = 0; m < TILE; m++) hs[m][t] = g_h[(m0+m)*DM + t];
    __syncthreads();

    float aq[TILE], ak[TILE], av[TILE];
    float bq = bias[t], bk = bias[t+128], bv = bias[t+256];
    #pragma unroll
    for (int m = 0; m < TILE; m++) { aq[m]=bq; ak[m]=bk; av[m]=bv; }
    #pragma unroll 4
    for (int k = 0; k < DM; k++) {
        float wq = W[k*DQKV + t];
        float wk = W[k*DQKV + t + 128];
        float wv = W[k*DQKV + t + 256];
        #pragma unroll
        for (int m = 0; m < TILE; m++) {
            float x = hs[m][k];
            aq[m] = fmaf(x, wq, aq[m]);
            ak[m] = fmaf(x, wk, ak[m]);
            av[m] = fmaf(x, wv, av[m]);
        }
    }
    #pragma unroll
    for (int m = 0; m < TILE; m++) {
        int r = m0 + m;
        g_qkv[r*DQKV + t      ] = aq[m];
        g_qkv[r*DQKV + t + 128] = ak[m];
        g_qkv[r*DQKV + t + 256] = av[m];
    }
}

// ---------------------------------------------------------------------------
// Kernel 3: banded causal attention. 1 block = 1 query token, warp = head.
// ---------------------------------------------------------------------------
__global__ void k_attn()
{
    int r = blockIdx.x;
    int b = r >> 11;            // r / 2048
    int i = r & (TT - 1);
    int t = threadIdx.x;
    int h = t >> 5;
    int l = t & 31;

    __shared__ float qs[DM];
    __shared__ float sc[NH][WIN];

    qs[t] = g_qkv[r*DQKV + t];
    __syncthreads();

    int jstart = (i >= WIN-1) ? (i - WIN + 1) : 0;
    int nj = i - jstart + 1;    // 1..64
    const float scale = 0.17677669529663687f;   // 1/sqrt(32)
    const float* qh = qs + h*DH;

    float s0 = -INFINITY, s1 = -INFINITY;
    if (l < nj) {
        const float* kp = g_qkv + (size_t)(b*TT + jstart + l)*DQKV + 128 + h*DH;
        float a = 0.f;
        #pragma unroll
        for (int d = 0; d < DH; d++) a = fmaf(qh[d], kp[d], a);
        s0 = a * scale;
    }
    if (l + 32 < nj) {
        const float* kp = g_qkv + (size_t)(b*TT + jstart + l + 32)*DQKV + 128 + h*DH;
        float a = 0.f;
        #pragma unroll
        for (int d = 0; d < DH; d++) a = fmaf(qh[d], kp[d], a);
        s1 = a * scale;
    }

    // warp max
    float mx = fmaxf(s0, s1);
    #pragma unroll
    for (int off = 16; off > 0; off >>= 1)
        mx = fmaxf(mx, __shfl_xor_sync(0xffffffffu, mx, off));

    float p0 = (l      < nj) ? expf(s0 - mx) : 0.0f;
    float p1 = (l + 32 < nj) ? expf(s1 - mx) : 0.0f;
    sc[h][l]      = p0;
    sc[h][l + 32] = p1;
    float sum = p0 + p1;
    #pragma unroll
    for (int off = 16; off > 0; off >>= 1)
        sum += __shfl_xor_sync(0xffffffffu, sum, off);
    __syncwarp();

    // output: lane = head dim
    float acc = 0.f;
    const float* vbase = g_qkv + (size_t)(b*TT + jstart)*DQKV + 256 + h*DH + l;
    for (int jj = 0; jj < nj; jj++)
        acc = fmaf(sc[h][jj], vbase[(size_t)jj*DQKV], acc);

    g_att[r*DM + h*DH + l] = acc / sum;
}

// ---------------------------------------------------------------------------
// LayerNorm helper: 8 tokens in shared res[8][128], warp w handles tokens 2w,2w+1
// ---------------------------------------------------------------------------
__device__ __forceinline__ void block_ln_write(
    float (&res)[TILE][DM], float* muS, float* rsS,
    const float* __restrict__ g, const float* __restrict__ be,
    int m0, int t)
{
    int w = t >> 5, l = t & 31;
    #pragma unroll
    for (int s = 0; s < 2; s++) {
        int mm = w*2 + s;
        float v = res[mm][l] + res[mm][l+32] + res[mm][l+64] + res[mm][l+96];
        #pragma unroll
        for (int off = 16; off > 0; off >>= 1)
            v += __shfl_xor_sync(0xffffffffu, v, off);
        float mean = v * (1.0f/128.0f);
        float d0 = res[mm][l   ] - mean;
        float d1 = res[mm][l+32] - mean;
        float d2 = res[mm][l+64] - mean;
        float d3 = res[mm][l+96] - mean;
        float q = d0*d0 + d1*d1 + d2*d2 + d3*d3;
        #pragma unroll
        for (int off = 16; off > 0; off >>= 1)
            q += __shfl_xor_sync(0xffffffffu, q, off);
        if (l == 0) { muS[mm] = mean; rsS[mm] = rsqrtf(q * (1.0f/128.0f) + 1e-5f); }
    }
    __syncthreads();
    float gt = g[t], bt = be[t];
    #pragma unroll
    for (int mm = 0; mm < TILE; mm++) {
        float y = (res[mm][t] - muS[mm]) * rsS[mm] * gt + bt;
        g_h[(m0+mm)*DM + t] = y;
    }
}

// ---------------------------------------------------------------------------
// Kernel 4: o-proj + residual + LN1 :  h = LN(h + att @ Wo + bo)
// ---------------------------------------------------------------------------
__global__ void k_oproj_ln(const float* __restrict__ Wo, const float* __restrict__ bo,
                           const float* __restrict__ g, const float* __restrict__ be)
{
    int m0 = blockIdx.x * TILE;
    int t  = threadIdx.x;
    __shared__ float as[TILE][DM];
    __shared__ float res[TILE][DM];
    __shared__ float muS[TILE], rsS[TILE];

    #pragma unroll
    for (int m = 0; m < TILE; m++) as[m][t] = g_att[(m0+m)*DM + t];
    __syncthreads();

    float acc[TILE];
    float bv = bo[t];
    #pragma unroll
    for (int m = 0; m < TILE; m++) acc[m] = bv;
    #pragma unroll 8
    for (int k = 0; k < DM; k++) {
        float w = Wo[k*DM + t];
        #pragma unroll
        for (int m = 0; m < TILE; m++) acc[m] = fmaf(as[m][k], w, acc[m]);
    }
    #pragma unroll
    for (int m = 0; m < TILE; m++) res[m][t] = g_h[(m0+m)*DM + t] + acc[m];
    __syncthreads();

    block_ln_write(res, muS, rsS, g, be, m0, t);
}

// ---------------------------------------------------------------------------
// Kernel 5: FF + residual + LN2 :  h = LN(h + relu(h@W1+b1)@W2+b2)
// ---------------------------------------------------------------------------
__global__ void k_ff_ln(const float* __restrict__ W1, const float* __restrict__ b1,
                        const float* __restrict__ W2, const float* __restrict__ b2,
                        const float* __restrict__ g,  const float* __restrict__ be)
{
    int m0 = blockIdx.x * TILE;
    int t  = threadIdx.x;
    __shared__ float hs[TILE][DM];
    __shared__ float us[TILE][DFFN];
    __shared__ float muS[TILE], rsS[TILE];

    #pragma unroll
    for (int m = 0; m < TILE; m++) hs[m][t] = g_h[(m0+m)*DM + t];
    __syncthreads();

    // u = relu(h @ W1 + b1), 2 cols/thread
    {
        float a0[TILE], a1[TILE];
        float bv0 = b1[t], bv1 = b1[t+128];
        #pragma unroll
        for (int m = 0; m < TILE; m++) { a0[m] = bv0; a1[m] = bv1; }
        #pragma unroll 4
        for (int k = 0; k < DM; k++) {
            float w0 = W1[k*DFFN + t];
            float w1 = W1[k*DFFN + t + 128];
            #pragma unroll
            for (int m = 0; m < TILE; m++) {
                float x = hs[m][k];
                a0[m] = fmaf(x, w0, a0[m]);
                a1[m] = fmaf(x, w1, a1[m]);
            }
        }
        #pragma unroll
        for (int m = 0; m < TILE; m++) {
            us[m][t]     = fmaxf(a0[m], 0.0f);
            us[m][t+128] = fmaxf(a1[m], 0.0f);
        }
    }
    __syncthreads();

    // f = u @ W2 + b2, residual
    {
        float acc[TILE];
        float bv = b2[t];
        #pragma unroll
        for (int m = 0; m < TILE; m++) acc[m] = bv;
        #pragma unroll 8
        for (int k = 0; k < DFFN; k++) {
            float w = W2[k*DM + t];
            #pragma unroll
            for (int m = 0; m < TILE; m++) acc[m] = fmaf(us[m][k], w, acc[m]);
        }
        #pragma unroll
        for (int m = 0; m < TILE; m++) hs[m][t] += acc[m];   // reuse hs as residual
    }
    __syncthreads();

    block_ln_write(hs, muS, rsS, g, be, m0, t);
}

// ---------------------------------------------------------------------------
// Kernel 6: head  out = h @ W_head + b_head   (D_RHO = 8)
// ---------------------------------------------------------------------------
__global__ void k_head(const float* __restrict__ W, const float* __restrict__ bias,
                       float* __restrict__ out)
{
    int m0 = blockIdx.x * TILE;
    int t  = threadIdx.x;
    __shared__ float hs[TILE][DM];
    #pragma unroll
    for (int m = 0; m < TILE; m++) hs[m][t] = g_h[(m0+m)*DM + t];
    __syncthreads();

    if (t < TILE*8) {
        int m = t >> 3, c = t & 7;
        float acc = bias[c];
        #pragma unroll 8
        for (int k = 0; k < DM; k++) acc = fmaf(hs[m][k], W[k*8 + c], acc);
        out[(m0+m)*8 + c] = acc;
    }
}

// ---------------------------------------------------------------------------
extern "C" void kernel_launch(void* const* d_in, const int* in_sizes, int n_in,
                              void* d_out, int out_size)
{
    const float* E      = (const float*)d_in[0];
    const float* rho    = (const float*)d_in[1];
    const float* W_in1  = (const float*)d_in[2];
    const float* b_in1  = (const float*)d_in[3];
    const float* W_in2  = (const float*)d_in[4];
    const float* b_in2  = (const float*)d_in[5];
    const float* Wqkv   = (const float*)d_in[6];
    const float* bqkv   = (const float*)d_in[7];
    const float* Wo     = (const float*)d_in[8];
    const float* bo     = (const float*)d_in[9];
    const float* ln1g   = (const float*)d_in[10];
    const float* ln1b   = (const float*)d_in[11];
    const float* Wff1   = (const float*)d_in[12];
    const float* bff1   = (const float*)d_in[13];
    const float* Wff2   = (const float*)d_in[14];
    const float* bff2   = (const float*)d_in[15];
    const float* ln2g   = (const float*)d_in[16];
    const float* ln2b   = (const float*)d_in[17];
    const float* W_head = (const float*)d_in[18];
    const float* b_head = (const float*)d_in[19];
    float* out = (float*)d_out;

    k_inproj<<<NBLK, 128>>>(E, rho, W_in1, b_in1, W_in2, b_in2);

    for (int l = 0; l < 3; l++) {
        k_qkv<<<NBLK, 128>>>(Wqkv + (size_t)l*DM*DQKV, bqkv + l*DQKV);
        k_attn<<<NTOK, 128>>>();
        k_oproj_ln<<<NBLK, 128>>>(Wo + (size_t)l*DM*DM, bo + l*DM,
                                  ln1g + l*DM, ln1b + l*DM);
        k_ff_ln<<<NBLK, 128>>>(Wff1 + (size_t)l*DM*DFFN, bff1 + l*DFFN,
                               Wff2 + (size_t)l*DFFN*DM, bff2 + l*DM,
                               ln2g + l*DM, ln2b + l*DM);
    }

    k_head<<<NBLK, 128>>>(W_head, b_head, out);
}

// round 8
// speedup vs baseline: 2.6619x; 2.6619x over previous
#include <cuda_runtime.h>
#include <math.h>

#define BB     4
#define TT     2048
#define NTOK   (BB*TT)          // 8192
#define DM     128
#define NH     4
#define DH     32
#define WIN    64
#define DFFN   256
#define DQKV   384
#define TILE   16               // tokens per block in fused GEMM kernels
#define NBLK   (NTOK/TILE)      // 512

// Scratch (no cudaMalloc allowed)
__device__ float g_h[NTOK*DM];       // 4 MB
__device__ float g_qkv[NTOK*DQKV];   // 12 MB
__device__ float g_att[NTOK*DM];     // 4 MB

// ===========================================================================
// Kernel 1: in_proj (concat->Lin16x128->ReLU->Lin128x128 + PE) + QKV layer 0
// 256 threads: group g=t>>7 handles tokens g*8..g*8+7, channel c=t&127
// ===========================================================================
__global__ void __launch_bounds__(256, 4)
k_pre(const float* __restrict__ E,  const float* __restrict__ rho,
      const float* __restrict__ W1, const float* __restrict__ b1,
      const float* __restrict__ W2, const float* __restrict__ b2,
      const float* __restrict__ Wq, const float* __restrict__ bq)
{
    __shared__ float xs[TILE][16];
    __shared__ float sHid[TILE][DM];
    __shared__ float sH[TILE][DM];
    int t = threadIdx.x;
    int m0 = blockIdx.x * TILE;

    // load concat(E, rho): 256 elements, one per thread
    {
        int m = t >> 4, k = t & 15;
        int r = m0 + m;
        xs[m][k] = (k < 8) ? E[r*8 + k] : rho[r*8 + (k-8)];
    }
    __syncthreads();

    int g = t >> 7, c = t & 127;
    int mb = g * 8;

    // hidden = relu(x @ W1 + b1)
    {
        float acc[8];
        float bv = b1[c];
        #pragma unroll
        for (int m = 0; m < 8; m++) acc[m] = bv;
        #pragma unroll
        for (int k0 = 0; k0 < 16; k0 += 4) {
            float w0 = W1[(k0+0)*DM + c];
            float w1 = W1[(k0+1)*DM + c];
            float w2 = W1[(k0+2)*DM + c];
            float w3 = W1[(k0+3)*DM + c];
            #pragma unroll
            for (int m = 0; m < 8; m++) {
                float4 x = *(const float4*)&xs[mb+m][k0];
                acc[m] = fmaf(x.x, w0, fmaf(x.y, w1, fmaf(x.z, w2, fmaf(x.w, w3, acc[m]))));
            }
        }
        #pragma unroll
        for (int m = 0; m < 8; m++) sHid[mb+m][c] = fmaxf(acc[m], 0.0f);
    }
    __syncthreads();

    // h = hidden @ W2 + b2 + PE
    {
        float acc[8];
        float bv = b2[c];
        #pragma unroll
        for (int m = 0; m < 8; m++) acc[m] = bv;
        #pragma unroll 4
        for (int k0 = 0; k0 < DM; k0 += 4) {
            float w0 = W2[(k0+0)*DM + c];
            float w1 = W2[(k0+1)*DM + c];
            float w2 = W2[(k0+2)*DM + c];
            float w3 = W2[(k0+3)*DM + c];
            #pragma unroll
            for (int m = 0; m < 8; m++) {
                float4 x = *(const float4*)&sHid[mb+m][k0];
                acc[m] = fmaf(x.x, w0, fmaf(x.y, w1, fmaf(x.z, w2, fmaf(x.w, w3, acc[m]))));
            }
        }
        int i = c >> 1;
        float invf = expf(-9.210340371976184f * (float)i / 64.0f);
        #pragma unroll
        for (int m = 0; m < 8; m++) {
            int r = m0 + mb + m;
            int pos = r & (TT - 1);
            float ang = (float)pos * invf;
            float pe = (c & 1) ? cosf(ang) : sinf(ang);
            float h = acc[m] + pe;
            sH[mb+m][c] = h;
            g_h[r*DM + c] = h;
        }
    }
    __syncthreads();

    // QKV for layer 0
    #pragma unroll
    for (int pass = 0; pass < 3; pass++) {
        int off = pass * DM;
        float acc[8];
        float bv = bq[off + c];
        #pragma unroll
        for (int m = 0; m < 8; m++) acc[m] = bv;
        #pragma unroll 4
        for (int k0 = 0; k0 < DM; k0 += 4) {
            float w0 = Wq[(k0+0)*DQKV + off + c];
            float w1 = Wq[(k0+1)*DQKV + off + c];
            float w2 = Wq[(k0+2)*DQKV + off + c];
            float w3 = Wq[(k0+3)*DQKV + off + c];
            #pragma unroll
            for (int m = 0; m < 8; m++) {
                float4 x = *(const float4*)&sH[mb+m][k0];
                acc[m] = fmaf(x.x, w0, fmaf(x.y, w1, fmaf(x.z, w2, fmaf(x.w, w3, acc[m]))));
            }
        }
        #pragma unroll
        for (int m = 0; m < 8; m++)
            g_qkv[(m0+mb+m)*DQKV + off + c] = acc[m];
    }
}

// ===========================================================================
// Kernel 2: tiled banded attention.
// Block = (qtile of 32, head, batch). 256 threads (8 warps, 4 queries/warp).
// K transposed in shared (pad 97 -> conflict-free), V row-major, Q staged.
// ===========================================================================
__global__ void __launch_bounds__(256, 4)
k_attn()
{
    int qt = blockIdx.x, h = blockIdx.y, b = blockIdx.z;
    int t = threadIdx.x, w = t >> 5, l = t & 31;
    int qstart = qt * 32;
    int r0 = (qstart >= WIN-1) ? (qstart - (WIN-1)) : 0;
    int nrows = qstart + 32 - r0;           // <= 95

    __shared__ float KT[DH][97];
    __shared__ float Vs[95][DH];
    __shared__ float qs[32][DH];
    __shared__ float ps[8][WIN];

    const float* baseQ = g_qkv + (size_t)(b*TT + qstart)*DQKV + h*DH;
    for (int idx = t; idx < 32*DH; idx += 256) {
        int qi = idx >> 5, d = idx & 31;
        qs[qi][d] = baseQ[qi*DQKV + d];
    }
    const float* baseK = g_qkv + (size_t)(b*TT + r0)*DQKV + DM + h*DH;
    const float* baseV = baseK + DM;
    for (int idx = t; idx < nrows*DH; idx += 256) {
        int r = idx >> 5, d = idx & 31;
        KT[d][r] = baseK[r*DQKV + d];
        Vs[r][d] = baseV[r*DQKV + d];
    }
    __syncthreads();

    const float scale = 0.17677669529663687f;   // 1/sqrt(32)

    #pragma unroll
    for (int s = 0; s < 4; s++) {
        int qi = w*4 + s;
        int iglob = qstart + qi;
        int jlo = (iglob >= WIN-1) ? (iglob - (WIN-1)) : 0;
        int ni = iglob - jlo + 1;           // 1..64
        int base = jlo - r0;                // >= 0, base+63 <= nrows-1

        float a0 = 0.f, a1 = 0.f;
        #pragma unroll
        for (int d = 0; d < DH; d++) {
            float q = qs[qi][d];
            a0 = fmaf(q, KT[d][base + l],      a0);
            a1 = fmaf(q, KT[d][base + l + 32], a1);
        }
        a0 = (l      < ni) ? a0*scale : -1e30f;
        a1 = (l + 32 < ni) ? a1*scale : -1e30f;

        float mx = fmaxf(a0, a1);
        #pragma unroll
        for (int off = 16; off > 0; off >>= 1)
            mx = fmaxf(mx, __shfl_xor_sync(0xffffffffu, mx, off));

        float p0 = (l      < ni) ? __expf(a0 - mx) : 0.0f;
        float p1 = (l + 32 < ni) ? __expf(a1 - mx) : 0.0f;
        ps[w][l]      = p0;
        ps[w][l + 32] = p1;
        float sum = p0 + p1;
        #pragma unroll
        for (int off = 16; off > 0; off >>= 1)
            sum += __shfl_xor_sync(0xffffffffu, sum, off);
        __syncwarp();

        // AV: lane = head dim, 4 independent accumulator chains
        float acc0 = 0.f, acc1 = 0.f, acc2 = 0.f, acc3 = 0.f;
        int j = 0;
        for (; j + 3 < ni; j += 4) {
            acc0 = fmaf(ps[w][j],   Vs[base+j][l],   acc0);
            acc1 = fmaf(ps[w][j+1], Vs[base+j+1][l], acc1);
            acc2 = fmaf(ps[w][j+2], Vs[base+j+2][l], acc2);
            acc3 = fmaf(ps[w][j+3], Vs[base+j+3][l], acc3);
        }
        for (; j < ni; j++)
            acc0 = fmaf(ps[w][j], Vs[base+j][l], acc0);

        float rs = 1.0f / sum;
        g_att[(size_t)(b*TT + iglob)*DM + h*DH + l] = ((acc0+acc1) + (acc2+acc3)) * rs;
        __syncwarp();
    }
}

// ===========================================================================
// LayerNorm over 16 tokens, 256 threads. sR -> sOut (normalized).
// ===========================================================================
__device__ __forceinline__ void ln_16(float (&sR)[TILE][DM], float (&sOut)[TILE][DM],
                                      float* muS, float* rsS,
                                      const float* __restrict__ gw,
                                      const float* __restrict__ bw, int t)
{
    int w = t >> 5, l = t & 31;
    #pragma unroll
    for (int s = 0; s < 2; s++) {
        int mm = w*2 + s;
        float v = sR[mm][l] + sR[mm][l+32] + sR[mm][l+64] + sR[mm][l+96];
        #pragma unroll
        for (int off = 16; off > 0; off >>= 1)
            v += __shfl_xor_sync(0xffffffffu, v, off);
        float mean = v * (1.0f/128.0f);
        float d0 = sR[mm][l   ] - mean;
        float d1 = sR[mm][l+32] - mean;
        float d2 = sR[mm][l+64] - mean;
        float d3 = sR[mm][l+96] - mean;
        float q = d0*d0 + d1*d1 + d2*d2 + d3*d3;
        #pragma unroll
        for (int off = 16; off > 0; off >>= 1)
            q += __shfl_xor_sync(0xffffffffu, q, off);
        if (l == 0) { muS[mm] = mean; rsS[mm] = rsqrtf(q * (1.0f/128.0f) + 1e-5f); }
    }
    __syncthreads();
    int g = t >> 7, c = t & 127;
    float gg = gw[c], bb = bw[c];
    #pragma unroll
    for (int m = 0; m < 8; m++) {
        int mm = g*8 + m;
        sOut[mm][c] = (sR[mm][c] - muS[mm]) * rsS[mm] * gg + bb;
    }
    __syncthreads();
}

// ===========================================================================
// Kernel 3: fused post-attention block:
//   h = LN1(h + att@Wo + bo);  h = LN2(h + relu(h@Wf1+bf1)@Wf2 + bf2)
//   then QKV for next layer (last==0) or head output (last==1)
// ===========================================================================
__global__ void __launch_bounds__(256, 4)
k_post(const float* __restrict__ Wo,  const float* __restrict__ bo,
       const float* __restrict__ g1,  const float* __restrict__ b1n,
       const float* __restrict__ Wf1, const float* __restrict__ bf1,
       const float* __restrict__ Wf2, const float* __restrict__ bf2,
       const float* __restrict__ g2,  const float* __restrict__ b2n,
       const float* __restrict__ Wq,  const float* __restrict__ bq,
       const float* __restrict__ Wh,  const float* __restrict__ bh,
       float* __restrict__ out, int last)
{
    __shared__ float sH[TILE][DM];
    __shared__ float sA[TILE][DM];
    __shared__ float sR[TILE][DM];
    __shared__ float sU[TILE][DFFN];
    __shared__ float muS[TILE], rsS[TILE];

    int t = threadIdx.x;
    int m0 = blockIdx.x * TILE;
    int g = t >> 7, c = t & 127;
    int mb = g * 8;

    for (int idx = t; idx < TILE*DM; idx += 256) {
        int m = idx >> 7, cc = idx & 127;
        sH[m][cc] = g_h  [(m0+m)*DM + cc];
        sA[m][cc] = g_att[(m0+m)*DM + cc];
    }
    __syncthreads();

    // oproj + residual
    {
        float acc[8];
        float bv = bo[c];
        #pragma unroll
        for (int m = 0; m < 8; m++) acc[m] = bv;
        #pragma unroll 4
        for (int k0 = 0; k0 < DM; k0 += 4) {
            float w0 = Wo[(k0+0)*DM + c];
            float w1 = Wo[(k0+1)*DM + c];
            float w2 = Wo[(k0+2)*DM + c];
            float w3 = Wo[(k0+3)*DM + c];
            #pragma unroll
            for (int m = 0; m < 8; m++) {
                float4 x = *(const float4*)&sA[mb+m][k0];
                acc[m] = fmaf(x.x, w0, fmaf(x.y, w1, fmaf(x.z, w2, fmaf(x.w, w3, acc[m]))));
            }
        }
        #pragma unroll
        for (int m = 0; m < 8; m++) sR[mb+m][c] = sH[mb+m][c] + acc[m];
    }
    __syncthreads();

    ln_16(sR, sH, muS, rsS, g1, b1n, t);   // sH = LN1 output

    // FF1: u = relu(h @ Wf1 + bf1); thread handles channels c and c+128
    {
        float a0[8], a1[8];
        float bv0 = bf1[c], bv1 = bf1[c+128];
        #pragma unroll
        for (int m = 0; m < 8; m++) { a0[m] = bv0; a1[m] = bv1; }
        #pragma unroll 4
        for (int k0 = 0; k0 < DM; k0 += 4) {
            float w00 = Wf1[(k0+0)*DFFN + c],   w01 = Wf1[(k0+0)*DFFN + c+128];
            float w10 = Wf1[(k0+1)*DFFN + c],   w11 = Wf1[(k0+1)*DFFN + c+128];
            float w20 = Wf1[(k0+2)*DFFN + c],   w21 = Wf1[(k0+2)*DFFN + c+128];
            float w30 = Wf1[(k0+3)*DFFN + c],   w31 = Wf1[(k0+3)*DFFN + c+128];
            #pragma unroll
            for (int m = 0; m < 8; m++) {
                float4 x = *(const float4*)&sH[mb+m][k0];
                a0[m] = fmaf(x.x, w00, fmaf(x.y, w10, fmaf(x.z, w20, fmaf(x.w, w30, a0[m]))));
                a1[m] = fmaf(x.x, w01, fmaf(x.y, w11, fmaf(x.z, w21, fmaf(x.w, w31, a1[m]))));
            }
        }
        #pragma unroll
        for (int m = 0; m < 8; m++) {
            sU[mb+m][c]     = fmaxf(a0[m], 0.0f);
            sU[mb+m][c+128] = fmaxf(a1[m], 0.0f);
        }
    }
    __syncthreads();

    // FF2 + residual
    {
        float acc[8];
        float bv = bf2[c];
        #pragma unroll
        for (int m = 0; m < 8; m++) acc[m] = bv;
        #pragma unroll 4
        for (int k0 = 0; k0 < DFFN; k0 += 4) {
            float w0 = Wf2[(k0+0)*DM + c];
            float w1 = Wf2[(k0+1)*DM + c];
            float w2 = Wf2[(k0+2)*DM + c];
            float w3 = Wf2[(k0+3)*DM + c];
            #pragma unroll
            for (int m = 0; m < 8; m++) {
                float4 x = *(const float4*)&sU[mb+m][k0];
                acc[m] = fmaf(x.x, w0, fmaf(x.y, w1, fmaf(x.z, w2, fmaf(x.w, w3, acc[m]))));
            }
        }
        #pragma unroll
        for (int m = 0; m < 8; m++) sR[mb+m][c] = sH[mb+m][c] + acc[m];
    }
    __syncthreads();

    ln_16(sR, sH, muS, rsS, g2, b2n, t);   // sH = LN2 output = new h

    if (!last) {
        // write new h + QKV for next layer
        #pragma unroll
        for (int m = 0; m < 8; m++) g_h[(m0+mb+m)*DM + c] = sH[mb+m][c];

        #pragma unroll
        for (int pass = 0; pass < 3; pass++) {
            int off = pass * DM;
            float acc[8];
            float bv = bq[off + c];
            #pragma unroll
            for (int m = 0; m < 8; m++) acc[m] = bv;
            #pragma unroll 4
            for (int k0 = 0; k0 < DM; k0 += 4) {
                float w0 = Wq[(k0+0)*DQKV + off + c];
                float w1 = Wq[(k0+1)*DQKV + off + c];
                float w2 = Wq[(k0+2)*DQKV + off + c];
                float w3 = Wq[(k0+3)*DQKV + off + c];
                #pragma unroll
                for (int m = 0; m < 8; m++) {
                    float4 x = *(const float4*)&sH[mb+m][k0];
                    acc[m] = fmaf(x.x, w0, fmaf(x.y, w1, fmaf(x.z, w2, fmaf(x.w, w3, acc[m]))));
                }
            }
            #pragma unroll
            for (int m = 0; m < 8; m++)
                g_qkv[(m0+mb+m)*DQKV + off + c] = acc[m];
        }
    } else {
        // head: 16 tokens x 8 outputs = 128 values
        if (t < TILE*8) {
            int m = t >> 3, cc = t & 7;
            float acc = bh[cc];
            #pragma unroll 8
            for (int k = 0; k < DM; k++)
                acc = fmaf(sH[m][k], Wh[k*8 + cc], acc);
            out[(m0+m)*8 + cc] = acc;
        }
    }
}

// ===========================================================================
extern "C" void kernel_launch(void* const* d_in, const int* in_sizes, int n_in,
                              void* d_out, int out_size)
{
    const float* E      = (const float*)d_in[0];
    const float* rho    = (const float*)d_in[1];
    const float* W_in1  = (const float*)d_in[2];
    const float* b_in1  = (const float*)d_in[3];
    const float* W_in2  = (const float*)d_in[4];
    const float* b_in2  = (const float*)d_in[5];
    const float* Wqkv   = (const float*)d_in[6];
    const float* bqkv   = (const float*)d_in[7];
    const float* Wo     = (const float*)d_in[8];
    const float* bo     = (const float*)d_in[9];
    const float* ln1g   = (const float*)d_in[10];
    const float* ln1b   = (const float*)d_in[11];
    const float* Wff1   = (const float*)d_in[12];
    const float* bff1   = (const float*)d_in[13];
    const float* Wff2   = (const float*)d_in[14];
    const float* bff2   = (const float*)d_in[15];
    const float* ln2g   = (const float*)d_in[16];
    const float* ln2b   = (const float*)d_in[17];
    const float* W_head = (const float*)d_in[18];
    const float* b_head = (const float*)d_in[19];
    float* out = (float*)d_out;

    k_pre<<<NBLK, 256>>>(E, rho, W_in1, b_in1, W_in2, b_in2, Wqkv, bqkv);

    dim3 agrid(TT/32, NH, BB);
    for (int l = 0; l < 3; l++) {
        k_attn<<<agrid, 256>>>();
        int last = (l == 2);
        k_post<<<NBLK, 256>>>(Wo + (size_t)l*DM*DM, bo + l*DM,
                              ln1g + l*DM, ln1b + l*DM,
                              Wff1 + (size_t)l*DM*DFFN, bff1 + l*DFFN,
                              Wff2 + (size_t)l*DFFN*DM, bff2 + l*DM,
                              ln2g + l*DM, ln2b + l*DM,
                              Wqkv + (size_t)(l+1)*DM*DQKV, bqkv + (l+1)*DQKV,
                              W_head, b_head, out, last);
    }
}